// round 17
// baseline (speedup 1.0000x reference)
#include <cuda_runtime.h>
#include <cuda_bf16.h>
#include <cstdint>
#include <math.h>

typedef unsigned long long ull;
typedef uint32_t u32;

#define BB 64
#define SS 512
#define EE 256
#define HH 512
#define GG 2048
#define BSH (BB*SS*HH)
#define NBLK 128

// scan smem layout (32-bit word offsets)
#define WHI   0            // [40][260] bf16x2 hi
#define WLO   10400        // [40][260] bf16x2 lo
#define XOFF  20800        // 4 planes (h_hi,h_lo,c_hi,c_lo) x [32][260]
#define XPL   8320
#define REDF  54080        // float red[40*65]
#define SMEM_WORDS 56680   // 226720 B
#define SCAN_SMEM (SMEM_WORDS*4)

__device__ float g_uproj[BB*SS*GG];
__device__ u32   g_xplane[4][BB][256];   // packed bf16x2: h_hi,h_lo,c_hi,c_lo
__device__ float g_cfp[BB*HH];
__device__ unsigned int g_ctr;

// ---------------- helpers ----------------
__device__ __forceinline__ void ffma2(ull& d, ull a, ull b) {
    asm("fma.rn.f32x2 %0, %1, %2, %0;" : "+l"(d) : "l"(a), "l"(b));
}
__device__ __forceinline__ ull dup2(float a) {
    ull r; asm("mov.b64 %0, {%1,%1};" : "=l"(r) : "f"(a)); return r;
}
__device__ __forceinline__ float sigf(float x) { return 1.0f / (1.0f + expf(-x)); }
__device__ __forceinline__ void mma16816(float* c, u32 a0, u32 a1, u32 a2, u32 a3, u32 b0, u32 b1) {
    asm volatile(
        "mma.sync.aligned.m16n8k16.row.col.f32.bf16.bf16.f32 "
        "{%0,%1,%2,%3}, {%4,%5,%6,%7}, {%8,%9}, {%0,%1,%2,%3};"
        : "+f"(c[0]), "+f"(c[1]), "+f"(c[2]), "+f"(c[3])
        : "r"(a0), "r"(a1), "r"(a2), "r"(a3), "r"(b0), "r"(b1));
}
__device__ __forceinline__ u32 packbf(float x, float y) {
    __nv_bfloat16 bx = __float2bfloat16(x);
    __nv_bfloat16 by = __float2bfloat16(y);
    return (u32)__bfloat16_as_ushort(bx) | ((u32)__bfloat16_as_ushort(by) << 16);
}

// ---------------- u_proj GEMM (FFMA2) fused with state init ----------------
__global__ void __launch_bounds__(256) gemm_uproj_init(
    const float* __restrict__ A, const float* __restrict__ W, const float* __restrict__ bias)
{
    __shared__ float As[8][132];
    __shared__ float Bs[8][132];
    const int tid = threadIdx.x;

    {
        const int flat = blockIdx.y * gridDim.x + blockIdx.x;
        if (flat < 128) {
            int i = flat * 256 + tid;           // 0..32767
            ((u32*)g_xplane)[i] = 0u;           // planes: 65536 words total
            ((u32*)g_xplane)[i + 32768] = 0u;
            g_cfp[i] = 0.f;
            if (i == 0) g_ctr = 0u;
        }
    }

    const int bm = blockIdx.y * 128, bn = blockIdx.x * 128;
    const int tx = tid & 15, ty = tid >> 4;
    const int lrow = tid >> 1, lk = (tid & 1) * 4;
    const float* Aptr = A + (size_t)(bm + lrow) * EE + lk;
    const float* Wptr = W + (size_t)(bn + lrow) * EE + lk;

    ull acc2[8][4];
#pragma unroll
    for (int r = 0; r < 8; r++)
#pragma unroll
        for (int c = 0; c < 4; c++) acc2[r][c] = 0ull;

    float4 av = *(const float4*)(Aptr);
    float4 bv = *(const float4*)(Wptr);

    for (int k0 = 0; k0 < EE; k0 += 8) {
        __syncthreads();
        As[lk+0][lrow]=av.x; As[lk+1][lrow]=av.y; As[lk+2][lrow]=av.z; As[lk+3][lrow]=av.w;
        Bs[lk+0][lrow]=bv.x; Bs[lk+1][lrow]=bv.y; Bs[lk+2][lrow]=bv.z; Bs[lk+3][lrow]=bv.w;
        __syncthreads();
        if (k0 + 8 < EE) { av = *(const float4*)(Aptr+k0+8); bv = *(const float4*)(Wptr+k0+8); }
#pragma unroll
        for (int kk = 0; kk < 8; kk++) {
            float4 a0 = *(const float4*)&As[kk][ty*8];
            float4 a1 = *(const float4*)&As[kk][ty*8+4];
            ulonglong2 b0 = *(const ulonglong2*)&Bs[kk][tx*8];
            ulonglong2 b1 = *(const ulonglong2*)&Bs[kk][tx*8+4];
            float ar[8] = {a0.x,a0.y,a0.z,a0.w,a1.x,a1.y,a1.z,a1.w};
            ull br2[4] = {b0.x, b0.y, b1.x, b1.y};
#pragma unroll
            for (int r = 0; r < 8; r++) {
                ull ad = dup2(ar[r]);
#pragma unroll
                for (int c = 0; c < 4; c++) ffma2(acc2[r][c], ad, br2[c]);
            }
        }
    }

    float bsr[8];
#pragma unroll
    for (int c = 0; c < 8; c++) bsr[c] = bias[bn + tx*8 + c];
#pragma unroll
    for (int r = 0; r < 8; r++) {
        float accv[8];
#pragma unroll
        for (int c = 0; c < 4; c++) {
            float lo, hi;
            asm("mov.b64 {%0,%1}, %2;" : "=f"(lo), "=f"(hi) : "l"(acc2[r][c]));
            accv[2*c] = lo; accv[2*c+1] = hi;
        }
        float* cp = g_uproj + (size_t)(bm + ty*8 + r) * GG + bn + tx*8;
        float4 o0 = {accv[0]+bsr[0], accv[1]+bsr[1], accv[2]+bsr[2], accv[3]+bsr[3]};
        float4 o1 = {accv[4]+bsr[4], accv[5]+bsr[5], accv[6]+bsr[6], accv[7]+bsr[7]};
        *(float4*)(cp) = o0; *(float4*)(cp + 4) = o1;
    }
}

// ---------------- persistent scan: bf16 3-pass mma.sync ----------------
// Block: jg = bid>>1 (8 j), bg = bid&1 (32 b).
// D rows 0..39 = gate*8+jj (f,i,o,cT use h; wd rows 32-39 use c).
// Warp w: ntile = w&3 (8 b-cols), khalf = w>>2 (256 k). Lane: g = lane>>2, t = lane&3.
// m-tiles: 0 = rows 0-15, 1 = rows 16-31 (B = h); 2 = rows 32-39 (+pad, B = c).
__global__ void __launch_bounds__(256, 1) lstm_scan(
    const float* __restrict__ ts,
    const float* __restrict__ Wall,
    const float* __restrict__ ball,
    const float* __restrict__ Wd,
    const float* __restrict__ bd,
    float* __restrict__ out)
{
    extern __shared__ float sm[];
    u32* smu = (u32*)sm;
    const int tid = threadIdx.x;
    const int bid = blockIdx.x;
    const int jbase = (bid >> 1) * 8;
    const int bbase = (bid & 1) * 32;

    // ---- weights -> bf16 hi/lo packed smem, once ----
    for (int idx = tid; idx < 40*256; idx += 256) {
        int row = idx >> 8, pr = idx & 255;
        int t4 = row >> 3, jr = jbase + (row & 7);
        const float* src = (t4 < 4) ? (Wall + (size_t)(t4*512 + jr)*512 + pr*2)
                                    : (Wd + (size_t)jr*512 + pr*2);
        float2 wv = *(const float2*)src;
        __nv_bfloat16 h0 = __float2bfloat16(wv.x);
        __nv_bfloat16 h1 = __float2bfloat16(wv.y);
        float l0f = wv.x - __bfloat162float(h0);
        float l1f = wv.y - __bfloat162float(h1);
        smu[WHI + row*260 + pr] = (u32)__bfloat16_as_ushort(h0) | ((u32)__bfloat16_as_ushort(h1) << 16);
        smu[WLO + row*260 + pr] = packbf(l0f, l1f);
    }

    // compute identity
    const int w     = tid >> 5;
    const int lane  = tid & 31;
    const int ntile = w & 3;
    const int khalf = w >> 2;
    const int g     = lane >> 2;
    const int t     = lane & 3;

    // staging identity: plane p, row r, half
    const int sp = tid >> 6;          // 0..3
    const int sr = (tid >> 1) & 31;   // 0..31
    const int sh = tid & 1;           // 0/1

    // phase-B identity
    const int pb = tid >> 3;
    const int pj = tid & 7;
    const int b2 = bbase + pb;
    const int j  = jbase + pj;
    const float bfb = __ldg(ball + j);
    const float bib = __ldg(ball + 512 + j);
    const float bob = __ldg(ball + 1024 + j);
    const float bcb = __ldg(ball + 1536 + j);
    const float bdj = __ldg(bd + j);

    __syncthreads();

    for (int s = 0; s < SS; s++) {
        // phase-B operand prefetch
        const float* up = g_uproj + ((size_t)b2 * SS + s) * GG;
        float u0 = __ldg(up + j);
        float u1 = __ldg(up + 512 + j);
        float u2 = __ldg(up + 1024 + j);
        float u3 = __ldg(up + 1536 + j);
        float tv = __ldg(ts + b2 * SS + s);
        float c_old = g_cfp[b2 * HH + j];

        // ---- stage x planes (L2-coherent) ----
        {
            const uint4* src = (const uint4*)(&g_xplane[sp][bbase + sr][sh * 128]);
            u32* dst = smu + XOFF + sp*XPL + sr*260 + sh*128;
#pragma unroll 8
            for (int i = 0; i < 32; i++) {
                uint4 v = __ldcg(src + i);
                *(uint4*)(dst + 4*i) = v;
            }
        }
        __syncthreads();

        // ---- GEMM: 3-pass bf16 mma ----
        float C0[4] = {0,0,0,0}, C1[4] = {0,0,0,0}, C2[4] = {0,0,0,0};
        {
            const u32* xhh = smu + XOFF;
            const u32* xhl = smu + XOFF + XPL;
            const u32* xch = smu + XOFF + 2*XPL;
            const u32* xcl = smu + XOFF + 3*XPL;
#pragma unroll 1
            for (int pass = 0; pass < 3; pass++) {
                const u32* WA = smu + ((pass == 2) ? WLO : WHI) + khalf*128 + t;
                const u32* bh = ((pass == 1) ? xhl : xhh) + (ntile*8 + g)*260 + khalf*128;
                const u32* bc = ((pass == 1) ? xcl : xch) + (ntile*8 + g)*260 + khalf*128;
#pragma unroll 4
                for (int q = 0; q < 16; q++) {
                    const int ko = q * 8;
                    u32 b0h = bh[ko + t], b1h = bh[ko + t + 4];
                    u32 b0c = bc[ko + t], b1c = bc[ko + t + 4];
                    u32 a0 = WA[(g)*260 + ko],      a1 = WA[(g+8)*260 + ko];
                    u32 a2 = WA[(g)*260 + ko + 4],  a3 = WA[(g+8)*260 + ko + 4];
                    mma16816(C0, a0, a1, a2, a3, b0h, b1h);
                    a0 = WA[(16+g)*260 + ko];      a1 = WA[(24+g)*260 + ko];
                    a2 = WA[(16+g)*260 + ko + 4];  a3 = WA[(24+g)*260 + ko + 4];
                    mma16816(C1, a0, a1, a2, a3, b0h, b1h);
                    a0 = WA[(32+g)*260 + ko];      a2 = WA[(32+g)*260 + ko + 4];
                    mma16816(C2, a0, 0u, a2, 0u, b0c, b1c);
                }
            }
        }

        // ---- write partials: red[row*65 + col*2 + khalf] ----
        {
            float* red = sm + REDF;
            const int colb = (ntile*8 + 2*t) * 2 + khalf;
            red[(g)*65 + colb]          = C0[0];
            red[(g)*65 + colb + 2]      = C0[1];
            red[(g+8)*65 + colb]        = C0[2];
            red[(g+8)*65 + colb + 2]    = C0[3];
            red[(16+g)*65 + colb]       = C1[0];
            red[(16+g)*65 + colb + 2]   = C1[1];
            red[(24+g)*65 + colb]       = C1[2];
            red[(24+g)*65 + colb + 2]   = C1[3];
            red[(32+g)*65 + colb]       = C2[0];
            red[(32+g)*65 + colb + 2]   = C2[1];
        }
        __syncthreads();

        // ---- phase B ----
        {
            const float* red = sm + REDF;
            float p[5];
#pragma unroll
            for (int gt = 0; gt < 5; gt++) {
                const float* rp = red + (gt*8 + pj)*65 + pb*2;
                p[gt] = rp[0] + rp[1];
            }
            float dec  = 1.0f / logf(2.718281828459045f + tv);
            float cs1  = tanhf(p[4] + bdj);
            float cadj = (c_old - cs1) + cs1 * dec;
            float f  = sigf(p[0] + bfb + u0);
            float ii = sigf(p[1] + bib + u1);
            float o  = sigf(p[2] + bob + u2);
            float ct = tanhf(p[3] + bcb + u3);
            float cn = f * cadj + ii * ct;
            float hn = o * tanhf(cn);

            // bf16 hi/lo split + pair pack via shfl
            __nv_bfloat16 hh16 = __float2bfloat16(hn);
            float hhf = __bfloat162float(hh16);
            __nv_bfloat16 hl16 = __float2bfloat16(hn - hhf);
            __nv_bfloat16 ch16 = __float2bfloat16(cn);
            float chf = __bfloat162float(ch16);
            __nv_bfloat16 cl16 = __float2bfloat16(cn - chf);
            u32 hhB = (u32)__bfloat16_as_ushort(hh16);
            u32 hlB = (u32)__bfloat16_as_ushort(hl16);
            u32 chB = (u32)__bfloat16_as_ushort(ch16);
            u32 clB = (u32)__bfloat16_as_ushort(cl16);
            u32 nhh = __shfl_down_sync(0xffffffffu, hhB, 1);
            u32 nhl = __shfl_down_sync(0xffffffffu, hlB, 1);
            u32 nch = __shfl_down_sync(0xffffffffu, chB, 1);
            u32 ncl = __shfl_down_sync(0xffffffffu, clB, 1);
            if (!(pj & 1)) {
                int pairIdx = (jbase >> 1) + (pj >> 1);
                g_xplane[0][b2][pairIdx] = hhB | (nhh << 16);
                g_xplane[1][b2][pairIdx] = hlB | (nhl << 16);
                g_xplane[2][b2][pairIdx] = chB | (nch << 16);
                g_xplane[3][b2][pairIdx] = clB | (ncl << 16);
            }
            g_cfp[b2 * HH + j] = cn;
            out[((size_t)b2 * SS + s) * HH + j] = hn;
            if (s == SS - 1) {
                out[BSH + b2*HH + j] = hn;
                out[BSH + BB*HH + b2*HH + j] = cn;
            }
        }

        // ---- grid barrier ----
        if (s < SS - 1) {
            __threadfence();
            __syncthreads();
            if (tid == 0) {
                atomicAdd(&g_ctr, 1u);
                unsigned tgt = (unsigned)(s + 1) * NBLK;
                volatile unsigned* pc = &g_ctr;
                while (*pc < tgt) { }
            }
            __syncthreads();
        }
    }
}

extern "C" void kernel_launch(void* const* d_in, const int* in_sizes, int n_in,
                              void* d_out, int out_size) {
    const float* inputs = (const float*)d_in[0];
    const float* tstamp = (const float*)d_in[1];
    const float* Wall   = (const float*)d_in[2];
    const float* ball   = (const float*)d_in[3];
    const float* Uall   = (const float*)d_in[4];
    const float* uball  = (const float*)d_in[5];
    const float* Wd     = (const float*)d_in[6];
    const float* bd     = (const float*)d_in[7];
    float* out = (float*)d_out;

    cudaFuncSetAttribute(lstm_scan, cudaFuncAttributeMaxDynamicSharedMemorySize, SCAN_SMEM);

    dim3 g1(GG / 128, (BB * SS) / 128);
    gemm_uproj_init<<<g1, 256>>>(inputs, Uall, uball);
    lstm_scan<<<NBLK, 256, SCAN_SMEM>>>(tstamp, Wall, ball, Wd, bd, out);
}